// round 4
// baseline (speedup 1.0000x reference)
#include <cuda_runtime.h>
#include <math.h>

#define NN 50000
#define EE 800000
#define D  64
#define GG 64
#define BN_EPS 1e-5f
#define SCAN_BLOCKS 196   // ceil(50000/256)

// ---------------- device scratch (device-code access only) ----------------
__device__ int   g_degi  [NN];
__device__ float g_dinv  [NN];
__device__ int   g_rowptr[NN];
__device__ int   g_cursor[NN];
__device__ int   g_blocksum[256];
__device__ int   g_blockoff[256];
__device__ __align__(16) int2  g_csr[EE];       // (src, coef-as-int-bits)
__device__ __align__(16) float g_h1 [NN * D];   // h1 = x@W1
__device__ __align__(16) float g_agg[NN * D];   // pre-BN layer-1 result
__device__ __align__(16) float g_h2 [NN * D];   // h2 = act@W2
__device__ float g_bnsum[D];
__device__ float g_bnsq [D];
__device__ __align__(16) float g_pool[GG * D];
__device__ float g_cnt [GG];

// ---------------- packed f32x2 helpers (Blackwell double-rate fp32) ----------------
__device__ __forceinline__ unsigned long long pack2(float x, float y) {
    unsigned long long r;
    asm("mov.b64 %0, {%1, %2};" : "=l"(r) : "f"(x), "f"(y));
    return r;
}
__device__ __forceinline__ void ffma2(unsigned long long& d,
                                      unsigned long long a, unsigned long long b) {
    asm("fma.rn.f32x2 %0, %1, %2, %0;" : "+l"(d) : "l"(a), "l"(b));
}
__device__ __forceinline__ float2 unpack2(unsigned long long v) {
    float2 f;
    asm("mov.b64 {%0, %1}, %2;" : "=f"(f.x), "=f"(f.y) : "l"(v));
    return f;
}

// ---------------- zero the (small) accumulators ----------------
__global__ void zero_kernel() {
    int i = blockIdx.x * blockDim.x + threadIdx.x;
    if (i < NN)     g_degi[i] = 0;
    if (i < GG * D) g_pool[i] = 0.f;
    if (i < D)    { g_bnsum[i] = 0.f; g_bnsq[i] = 0.f; }
    if (i < GG)     g_cnt[i] = 0.f;
}

__global__ void degree_kernel(const int* __restrict__ dst) {
    int e = blockIdx.x * blockDim.x + threadIdx.x;
    if (e < EE) atomicAdd(&g_degi[dst[e]], 1);
}

// ---------------- scan phase 1 (+ fused dinv) ----------------
__global__ void scan1_kernel() {
    __shared__ int s[256];
    int idx = blockIdx.x * 256 + threadIdx.x;
    int dv = (idx < NN) ? g_degi[idx] : 0;
    if (idx < NN) g_dinv[idx] = rsqrtf((float)dv + 1.0f);
    s[threadIdx.x] = dv;
    __syncthreads();
    for (int o = 128; o > 0; o >>= 1) {
        if (threadIdx.x < o) s[threadIdx.x] += s[threadIdx.x + o];
        __syncthreads();
    }
    if (threadIdx.x == 0) g_blocksum[blockIdx.x] = s[0];
}

__global__ void scan2_kernel() {
    __shared__ int s[256];
    int t = threadIdx.x;
    int v = (t < SCAN_BLOCKS) ? g_blocksum[t] : 0;
    s[t] = v;
    __syncthreads();
    for (int o = 1; o < 256; o <<= 1) {
        int add = (t >= o) ? s[t - o] : 0;
        __syncthreads();
        s[t] += add;
        __syncthreads();
    }
    g_blockoff[t] = s[t] - v;
}

__global__ void scan3_kernel() {
    __shared__ int s[256];
    int t = threadIdx.x;
    int idx = blockIdx.x * 256 + t;
    int v = (idx < NN) ? g_degi[idx] : 0;
    s[t] = v;
    __syncthreads();
    for (int o = 1; o < 256; o <<= 1) {
        int add = (t >= o) ? s[t - o] : 0;
        __syncthreads();
        s[t] += add;
        __syncthreads();
    }
    if (idx < NN) {
        int rp = g_blockoff[blockIdx.x] + s[t] - v;
        g_rowptr[idx] = rp;
        g_cursor[idx] = rp;
    }
}

// ---------------- CSR fill: packed (src, coef) by dst ----------------
__global__ void csr_fill_kernel(const int* __restrict__ src,
                                const int* __restrict__ dst) {
    int e = blockIdx.x * blockDim.x + threadIdx.x;
    if (e >= EE) return;
    int s = src[e], d = dst[e];
    int pos = atomicAdd(&g_cursor[d], 1);
    float coef = g_dinv[s] * g_dinv[d];
    g_csr[pos] = make_int2(s, __float_as_int(coef));
}

// ---------------- GEMM: Y[NN,64] = X[NN,64] @ W[64,64], f32x2 math ----------------
// MODE 0: X = x (param), Y = g_h1.
// MODE 1: X = elu(bn(g_agg)) on load (BN params computed per block), Y = g_h2.
// blockDim (8,16) = 128 threads; each thread: 4 rows x 8 cols.
template<int MODE>
__global__ void gemm64_kernel(const float* __restrict__ Xp,
                              const float* __restrict__ W,
                              const float* __restrict__ gamma,
                              const float* __restrict__ beta) {
    const float* __restrict__ X = (MODE == 0) ? Xp : (const float*)g_agg;
    float* __restrict__       Y = (MODE == 0) ? g_h1 : g_h2;

    __shared__ __align__(16) float sX[64][68];   // 68-pad: 272B rows keep float4 aligned
    __shared__ __align__(16) float sW[64][64];
    __shared__ float s_scale[64], s_shift[64];

    int tid  = threadIdx.y * 8 + threadIdx.x;    // 0..127
    int row0 = blockIdx.x * 64;

    if (MODE == 1) {
        if (tid < 64) {
            float inv_n = 1.0f / (float)NN;
            float mu  = g_bnsum[tid] * inv_n;
            float var = g_bnsq[tid] * inv_n - mu * mu;
            float sc  = gamma[tid] * rsqrtf(var + BN_EPS);
            s_scale[tid] = sc;
            s_shift[tid] = beta[tid] - mu * sc;
        }
        __syncthreads();
    }

    // load W and X tiles (1024 float4 each, 8 per thread)
    #pragma unroll
    for (int t = tid; t < 1024; t += 128) {
        int r = t >> 4, c4 = (t & 15) << 2;
        *(float4*)(&sW[r][c4]) = *(const float4*)(W + r * 64 + c4);
    }
    #pragma unroll
    for (int t = tid; t < 1024; t += 128) {
        int r = t >> 4, c4 = (t & 15) << 2;
        float4 v = make_float4(0.f, 0.f, 0.f, 0.f);
        if (row0 + r < NN) v = *(const float4*)(X + (size_t)(row0 + r) * D + c4);
        if (MODE == 1) {
            v.x = v.x * s_scale[c4]     + s_shift[c4];
            v.y = v.y * s_scale[c4 + 1] + s_shift[c4 + 1];
            v.z = v.z * s_scale[c4 + 2] + s_shift[c4 + 2];
            v.w = v.w * s_scale[c4 + 3] + s_shift[c4 + 3];
            v.x = (v.x > 0.f) ? v.x : (__expf(v.x) - 1.0f);
            v.y = (v.y > 0.f) ? v.y : (__expf(v.y) - 1.0f);
            v.z = (v.z > 0.f) ? v.z : (__expf(v.z) - 1.0f);
            v.w = (v.w > 0.f) ? v.w : (__expf(v.w) - 1.0f);
        }
        *(float4*)(&sX[r][c4]) = v;
    }
    __syncthreads();

    int c0 = threadIdx.x * 8;      // 8 output cols
    int r0 = threadIdx.y * 4;      // 4 output rows
    unsigned long long acc[4][4];  // [row][colpair]
    #pragma unroll
    for (int r = 0; r < 4; r++)
        #pragma unroll
        for (int p = 0; p < 4; p++) acc[r][p] = 0ull;

    #pragma unroll
    for (int k0 = 0; k0 < 64; k0 += 4) {
        float4 xr[4];
        #pragma unroll
        for (int r = 0; r < 4; r++) xr[r] = *(const float4*)(&sX[r0 + r][k0]);
        #pragma unroll
        for (int kk = 0; kk < 4; kk++) {
            float4 wa = *(const float4*)(&sW[k0 + kk][c0]);
            float4 wb = *(const float4*)(&sW[k0 + kk][c0 + 4]);
            unsigned long long w0 = pack2(wa.x, wa.y), w1 = pack2(wa.z, wa.w);
            unsigned long long w2 = pack2(wb.x, wb.y), w3 = pack2(wb.z, wb.w);
            #pragma unroll
            for (int r = 0; r < 4; r++) {
                float xv = (kk == 0) ? xr[r].x : (kk == 1) ? xr[r].y
                         : (kk == 2) ? xr[r].z : xr[r].w;
                unsigned long long xx = pack2(xv, xv);
                ffma2(acc[r][0], xx, w0);
                ffma2(acc[r][1], xx, w1);
                ffma2(acc[r][2], xx, w2);
                ffma2(acc[r][3], xx, w3);
            }
        }
    }

    #pragma unroll
    for (int r = 0; r < 4; r++) {
        int row = row0 + r0 + r;
        if (row < NN) {
            float2 p0 = unpack2(acc[r][0]), p1 = unpack2(acc[r][1]);
            float2 p2 = unpack2(acc[r][2]), p3 = unpack2(acc[r][3]);
            *(float4*)(Y + (size_t)row * D + c0)     = make_float4(p0.x, p0.y, p1.x, p1.y);
            *(float4*)(Y + (size_t)row * D + c0 + 4) = make_float4(p2.x, p2.y, p3.x, p3.y);
        }
    }
}

// ---------------- gather aggregation: one warp per node, 2 edges/iter ----------------
// Lanes 0-15 process even edge of the pair, 16-31 the odd; each lane owns a
// float4 feature chunk (fl = lane&15). Halves merged by shfl_xor(16) at the end.
// MODE 0: h=g_h1 -> g_agg + BN stats.  MODE 1: h=g_h2 -> outp + fused mean-pool.
template<int MODE>
__global__ void aggregate_kernel(float* __restrict__ outp,
                                 const float* __restrict__ bias,
                                 const int* __restrict__ batch) {
    const float* __restrict__ h = (MODE == 0) ? g_h1 : g_h2;
    float* __restrict__ dstbuf  = (MODE == 0) ? g_agg : outp;

    int n    = (blockIdx.x * blockDim.x + threadIdx.x) >> 5;  // grid sized: n < NN
    int lane = threadIdx.x & 31;
    int half = lane >> 4;
    int fl   = lane & 15;

    int e0 = g_rowptr[n];
    int deg = g_degi[n];
    int e1 = e0 + deg;

    float4 acc = make_float4(0.f, 0.f, 0.f, 0.f);
    for (int base = e0; base < e1; base += 32) {
        int m = e1 - base; if (m > 32) m = 32;
        int2 ec = make_int2(0, 0);
        if (lane < m) ec = g_csr[base + lane];
        int   s_l = ec.x;
        float c_l = __int_as_float(ec.y);
        #pragma unroll 4
        for (int j = 0; j < m; j += 2) {
            int idx = j + half;
            int   s = __shfl_sync(0xffffffffu, s_l, idx);
            float c = __shfl_sync(0xffffffffu, c_l, idx);
            if (idx < m) {
                float4 v = ((const float4*)h)[(size_t)s * 16 + fl];
                acc.x = fmaf(c, v.x, acc.x);
                acc.y = fmaf(c, v.y, acc.y);
                acc.z = fmaf(c, v.z, acc.z);
                acc.w = fmaf(c, v.w, acc.w);
            }
        }
    }
    // merge the two half-warp accumulators
    acc.x += __shfl_xor_sync(0xffffffffu, acc.x, 16);
    acc.y += __shfl_xor_sync(0xffffffffu, acc.y, 16);
    acc.z += __shfl_xor_sync(0xffffffffu, acc.z, 16);
    acc.w += __shfl_xor_sync(0xffffffffu, acc.w, 16);

    // self-loop + bias, then store (lanes 0-15 own the final row)
    float di = g_dinv[n];
    float cs = di * di;
    if (half == 0) {
        float4 hv = ((const float4*)h)[(size_t)n * 16 + fl];
        float4 bv = ((const float4*)bias)[fl];
        acc.x = fmaf(cs, hv.x, acc.x) + bv.x;
        acc.y = fmaf(cs, hv.y, acc.y) + bv.y;
        acc.z = fmaf(cs, hv.z, acc.z) + bv.z;
        acc.w = fmaf(cs, hv.w, acc.w) + bv.w;
        ((float4*)dstbuf)[(size_t)n * 16 + fl] = acc;
    }

    if (MODE == 0) {
        __shared__ float s_sum[64], s_sq[64];
        if (threadIdx.x < 64) { s_sum[threadIdx.x] = 0.f; s_sq[threadIdx.x] = 0.f; }
        __syncthreads();
        if (half == 0) {
            atomicAdd(&s_sum[fl * 4],     acc.x);
            atomicAdd(&s_sum[fl * 4 + 1], acc.y);
            atomicAdd(&s_sum[fl * 4 + 2], acc.z);
            atomicAdd(&s_sum[fl * 4 + 3], acc.w);
            atomicAdd(&s_sq [fl * 4],     acc.x * acc.x);
            atomicAdd(&s_sq [fl * 4 + 1], acc.y * acc.y);
            atomicAdd(&s_sq [fl * 4 + 2], acc.z * acc.z);
            atomicAdd(&s_sq [fl * 4 + 3], acc.w * acc.w);
        }
        __syncthreads();
        if (threadIdx.x < 64) {
            atomicAdd(&g_bnsum[threadIdx.x], s_sum[threadIdx.x]);
            atomicAdd(&g_bnsq [threadIdx.x], s_sq [threadIdx.x]);
        }
    } else {
        int g = batch[n];
        if (lane == 0) atomicAdd(&g_cnt[g], 1.0f);
        if (half == 0)
            atomicAdd(((float4*)g_pool) + (size_t)g * 16 + fl, acc);
    }
}

__global__ void pool_div_kernel(float* __restrict__ rep) {
    int t = blockIdx.x * blockDim.x + threadIdx.x;
    if (t >= GG * D) return;
    int g = t >> 6;
    rep[t] = g_pool[t] / fmaxf(g_cnt[g], 1.0f);
}

// ---------------- launch ----------------
extern "C" void kernel_launch(void* const* d_in, const int* in_sizes, int n_in,
                              void* d_out, int out_size) {
    const float* x     = (const float*)d_in[0];
    const int*   ei    = (const int*)  d_in[1];
    const int*   batch = (const int*)  d_in[2];
    const float* W1    = (const float*)d_in[3];
    const float* b1    = (const float*)d_in[4];
    const float* gamma = (const float*)d_in[5];
    const float* beta  = (const float*)d_in[6];
    const float* W2    = (const float*)d_in[7];
    const float* b2    = (const float*)d_in[8];
    float* out = (float*)d_out;                 // [NN*D] node out, then [GG*D] graph rep
    const int* src = ei;
    const int* dst = ei + EE;

    const int TPB = 256;
    int edge_blocks = (EE + TPB - 1) / TPB;            // 3125
    int node_blocks = (NN + TPB - 1) / TPB;            // 196
    int gemm_blocks = (NN + 63) / 64;                  // 782
    int agg_blocks  = NN / 8;                          // 6250 (warp per node)

    zero_kernel<<<node_blocks, TPB>>>();
    degree_kernel<<<edge_blocks, TPB>>>(dst);
    scan1_kernel<<<SCAN_BLOCKS, 256>>>();              // also computes dinv
    scan2_kernel<<<1, 256>>>();
    scan3_kernel<<<SCAN_BLOCKS, 256>>>();
    csr_fill_kernel<<<edge_blocks, TPB>>>(src, dst);
    // layer 1
    gemm64_kernel<0><<<gemm_blocks, dim3(8, 16)>>>(x, W1, gamma, beta);
    aggregate_kernel<0><<<agg_blocks, TPB>>>(out, b1, batch);
    // layer 2 (BN finalize + BN+ELU fused into gemm X load)
    gemm64_kernel<1><<<gemm_blocks, dim3(8, 16)>>>(x, W2, gamma, beta);
    aggregate_kernel<1><<<agg_blocks, TPB>>>(out, b2, batch);
    // graph readout
    pool_div_kernel<<<(GG * D + TPB - 1) / TPB, TPB>>>(out + (size_t)NN * D);
}

// round 5
// speedup vs baseline: 1.0930x; 1.0930x over previous
#include <cuda_runtime.h>
#include <math.h>

#define NN 50000
#define EE 800000
#define D  64
#define GG 64
#define BN_EPS 1e-5f
#define SCAN_BLOCKS 196   // ceil(50000/256)

// ---------------- device scratch (device-code access only) ----------------
__device__ int   g_degi  [NN];
__device__ float g_dinv  [NN];
__device__ int   g_rowptr[NN];
__device__ int   g_cursor[NN];
__device__ int   g_blocksum[256];
__device__ __align__(16) int2  g_csr[EE];       // (src, coef-as-int-bits)
__device__ __align__(16) float g_h1 [NN * D];   // h1 = x@W1
__device__ __align__(16) float g_agg[NN * D];   // pre-BN layer-1 result
__device__ __align__(16) float g_h2 [NN * D];   // h2 = act@W2
__device__ float g_bnsum[D];
__device__ float g_bnsq [D];
__device__ __align__(16) float g_pool[GG * D];
__device__ float g_cnt [GG];

// ---------------- zero the (small) accumulators ----------------
__global__ void zero_kernel() {
    int i = blockIdx.x * blockDim.x + threadIdx.x;
    if (i < NN)     g_degi[i] = 0;
    if (i < GG * D) g_pool[i] = 0.f;
    if (i < D)    { g_bnsum[i] = 0.f; g_bnsq[i] = 0.f; }
    if (i < GG)     g_cnt[i] = 0.f;
}

__global__ void degree_kernel(const int* __restrict__ dst) {
    int e = blockIdx.x * blockDim.x + threadIdx.x;
    if (e < EE) atomicAdd(&g_degi[dst[e]], 1);
}

// ---------------- scan phase 1: block sums (+ fused dinv) ----------------
__global__ void scan1_kernel() {
    __shared__ int s[256];
    int idx = blockIdx.x * 256 + threadIdx.x;
    int dv = (idx < NN) ? g_degi[idx] : 0;
    if (idx < NN) g_dinv[idx] = rsqrtf((float)dv + 1.0f);
    s[threadIdx.x] = dv;
    __syncthreads();
    for (int o = 128; o > 0; o >>= 1) {
        if (threadIdx.x < o) s[threadIdx.x] += s[threadIdx.x + o];
        __syncthreads();
    }
    if (threadIdx.x == 0) g_blocksum[blockIdx.x] = s[0];
}

// ---------------- scan phase 2+3 fused: every block re-scans block sums ----------------
__global__ void scan23_kernel() {
    __shared__ int sb[256];
    __shared__ int s[256];
    int t = threadIdx.x;
    // inclusive scan of the 196 block sums (cheap, done redundantly per block)
    sb[t] = (t < SCAN_BLOCKS) ? g_blocksum[t] : 0;
    __syncthreads();
    for (int o = 1; o < 256; o <<= 1) {
        int a = (t >= o) ? sb[t - o] : 0;
        __syncthreads();
        sb[t] += a;
        __syncthreads();
    }
    int blockoff = (blockIdx.x == 0) ? 0 : sb[blockIdx.x - 1];
    // local inclusive scan of this block's degrees
    int idx = blockIdx.x * 256 + t;
    int v = (idx < NN) ? g_degi[idx] : 0;
    s[t] = v;
    __syncthreads();
    for (int o = 1; o < 256; o <<= 1) {
        int a = (t >= o) ? s[t - o] : 0;
        __syncthreads();
        s[t] += a;
        __syncthreads();
    }
    if (idx < NN) {
        int rp = blockoff + s[t] - v;   // exclusive
        g_rowptr[idx] = rp;
        g_cursor[idx] = rp;
    }
}

// ---------------- CSR fill: packed (src, coef) by dst ----------------
__global__ void csr_fill_kernel(const int* __restrict__ src,
                                const int* __restrict__ dst) {
    int e = blockIdx.x * blockDim.x + threadIdx.x;
    if (e >= EE) return;
    int s = src[e], d = dst[e];
    int pos = atomicAdd(&g_cursor[d], 1);
    float coef = g_dinv[s] * g_dinv[d];
    g_csr[pos] = make_int2(s, __float_as_int(coef));
}

// ---------------- GEMM: Y[NN,64] = X[NN,64] @ W[64,64] (R3 proven shape) ----------------
// MODE 0: X = x (param), Y = g_h1.
// MODE 1: X = elu(bn(g_agg)) on load (BN params recomputed per block), Y = g_h2.
// blockDim (16,16) = 256 threads; each thread: 4 rows x 4 cols.
template<int MODE>
__global__ void gemm64_kernel(const float* __restrict__ Xp,
                              const float* __restrict__ W,
                              const float* __restrict__ gamma,
                              const float* __restrict__ beta) {
    const float* __restrict__ X = (MODE == 0) ? Xp : (const float*)g_agg;
    float* __restrict__       Y = (MODE == 0) ? g_h1 : g_h2;

    __shared__ float sX[64][65];
    __shared__ __align__(16) float sW[64][64];
    __shared__ float s_scale[64], s_shift[64];

    int tid  = threadIdx.y * 16 + threadIdx.x;
    int row0 = blockIdx.x * 64;

    if (MODE == 1) {
        if (tid < 64) {
            float inv_n = 1.0f / (float)NN;
            float mu  = g_bnsum[tid] * inv_n;
            float var = g_bnsq[tid] * inv_n - mu * mu;
            float sc  = gamma[tid] * rsqrtf(var + BN_EPS);
            s_scale[tid] = sc;
            s_shift[tid] = beta[tid] - mu * sc;
        }
        __syncthreads();
    }

    #pragma unroll
    for (int t = tid * 4; t < 4096; t += 1024) {
        *(float4*)(&sW[t >> 6][t & 63]) = *(const float4*)(W + t);
    }
    #pragma unroll
    for (int t = tid * 4; t < 4096; t += 1024) {
        int r = t >> 6, c = t & 63;
        float4 v = make_float4(0.f, 0.f, 0.f, 0.f);
        if (row0 + r < NN) v = *(const float4*)(X + (size_t)(row0 + r) * D + c);
        if (MODE == 1) {
            v.x = v.x * s_scale[c]     + s_shift[c];
            v.y = v.y * s_scale[c + 1] + s_shift[c + 1];
            v.z = v.z * s_scale[c + 2] + s_shift[c + 2];
            v.w = v.w * s_scale[c + 3] + s_shift[c + 3];
            v.x = (v.x > 0.f) ? v.x : (__expf(v.x) - 1.0f);
            v.y = (v.y > 0.f) ? v.y : (__expf(v.y) - 1.0f);
            v.z = (v.z > 0.f) ? v.z : (__expf(v.z) - 1.0f);
            v.w = (v.w > 0.f) ? v.w : (__expf(v.w) - 1.0f);
        }
        sX[r][c] = v.x; sX[r][c + 1] = v.y; sX[r][c + 2] = v.z; sX[r][c + 3] = v.w;
    }
    __syncthreads();

    float acc[4][4] = {};
    int c0 = threadIdx.x * 4, r0 = threadIdx.y * 4;
    #pragma unroll 16
    for (int k = 0; k < 64; k++) {
        float4 w = *(const float4*)(&sW[k][c0]);
        #pragma unroll
        for (int r = 0; r < 4; r++) {
            float xv = sX[r0 + r][k];
            acc[r][0] += xv * w.x; acc[r][1] += xv * w.y;
            acc[r][2] += xv * w.z; acc[r][3] += xv * w.w;
        }
    }
    #pragma unroll
    for (int r = 0; r < 4; r++) {
        int row = row0 + r0 + r;
        if (row < NN)
            *(float4*)(Y + (size_t)row * D + c0) =
                make_float4(acc[r][0], acc[r][1], acc[r][2], acc[r][3]);
    }
}

// ---------------- gather aggregation: one warp per node (R3 proven shape) ----------------
// out[n] = sum_{e in CSR[n]} coef[e]*h[src[e]] + dinv[n]^2*h[n] + bias
// MODE 0: h=g_h1 -> g_agg + BN stats.  MODE 1: h=g_h2 -> outp + fused mean-pool.
template<int MODE>
__global__ void aggregate_kernel(float* __restrict__ outp,
                                 const float* __restrict__ bias,
                                 const int* __restrict__ batch) {
    const float* __restrict__ h = (MODE == 0) ? g_h1 : g_h2;
    float* __restrict__ dstbuf  = (MODE == 0) ? g_agg : outp;

    int n    = (blockIdx.x * blockDim.x + threadIdx.x) >> 5;  // grid sized: n < NN
    int lane = threadIdx.x & 31;

    int e0  = g_rowptr[n];
    int e1  = e0 + g_degi[n];

    float2 acc = make_float2(0.f, 0.f);
    for (int base = e0; base < e1; base += 32) {
        int m = e1 - base; if (m > 32) m = 32;
        int2 ec = make_int2(0, 0);
        if (lane < m) ec = g_csr[base + lane];
        int   s_l = ec.x;
        float c_l = __int_as_float(ec.y);
        for (int j = 0; j < m; j++) {
            int   s = __shfl_sync(0xffffffffu, s_l, j);
            float c = __shfl_sync(0xffffffffu, c_l, j);
            float2 v = ((const float2*)h)[(size_t)s * 32 + lane];
            acc.x = fmaf(c, v.x, acc.x);
            acc.y = fmaf(c, v.y, acc.y);
        }
    }
    // self-loop + bias
    float di = g_dinv[n];
    float cs = di * di;
    float2 hv = ((const float2*)h)[(size_t)n * 32 + lane];
    float2 bv = ((const float2*)bias)[lane];
    acc.x = fmaf(cs, hv.x, acc.x) + bv.x;
    acc.y = fmaf(cs, hv.y, acc.y) + bv.y;

    ((float2*)dstbuf)[(size_t)n * 32 + lane] = acc;

    if (MODE == 0) {
        __shared__ float s_sum[64], s_sq[64];
        if (threadIdx.x < 64) { s_sum[threadIdx.x] = 0.f; s_sq[threadIdx.x] = 0.f; }
        __syncthreads();
        atomicAdd(&s_sum[2 * lane],     acc.x);
        atomicAdd(&s_sum[2 * lane + 1], acc.y);
        atomicAdd(&s_sq [2 * lane],     acc.x * acc.x);
        atomicAdd(&s_sq [2 * lane + 1], acc.y * acc.y);
        __syncthreads();
        if (threadIdx.x < 64) {
            atomicAdd(&g_bnsum[threadIdx.x], s_sum[threadIdx.x]);
            atomicAdd(&g_bnsq [threadIdx.x], s_sq [threadIdx.x]);
        }
    } else {
        int g = batch[n];
        if (lane == 0) atomicAdd(&g_cnt[g], 1.0f);
        atomicAdd(((float2*)g_pool) + (size_t)g * 32 + lane, acc);
    }
}

__global__ void pool_div_kernel(float* __restrict__ rep) {
    int t = blockIdx.x * blockDim.x + threadIdx.x;
    if (t >= GG * D) return;
    int g = t >> 6;
    rep[t] = g_pool[t] / fmaxf(g_cnt[g], 1.0f);
}

// ---------------- side stream for capture-time fork/join ----------------
// Created once in a static ctor: host-side resources only (no device memory),
// device work is identical on every kernel_launch call.
struct SideCtx {
    cudaStream_t s2;
    cudaEvent_t evFork, evJoin;
    SideCtx() {
        cudaStreamCreateWithFlags(&s2, cudaStreamNonBlocking);
        cudaEventCreateWithFlags(&evFork, cudaEventDisableTiming);
        cudaEventCreateWithFlags(&evJoin, cudaEventDisableTiming);
    }
};
static SideCtx g_side;

// ---------------- launch ----------------
extern "C" void kernel_launch(void* const* d_in, const int* in_sizes, int n_in,
                              void* d_out, int out_size) {
    const float* x     = (const float*)d_in[0];
    const int*   ei    = (const int*)  d_in[1];
    const int*   batch = (const int*)  d_in[2];
    const float* W1    = (const float*)d_in[3];
    const float* b1    = (const float*)d_in[4];
    const float* gamma = (const float*)d_in[5];
    const float* beta  = (const float*)d_in[6];
    const float* W2    = (const float*)d_in[7];
    const float* b2    = (const float*)d_in[8];
    float* out = (float*)d_out;                 // [NN*D] node out, then [GG*D] graph rep
    const int* src = ei;
    const int* dst = ei + EE;

    const int TPB = 256;
    int edge_blocks = (EE + TPB - 1) / TPB;            // 3125
    int node_blocks = (NN + TPB - 1) / TPB;            // 196
    int gemm_blocks = (NN + 63) / 64;                  // 782
    int agg_blocks  = NN / 8;                          // 6250 (warp per node)

    // Fork: GEMM-1 (x @ W1) is independent of the CSR build — run it on a
    // side stream so the captured graph executes both branches concurrently.
    cudaEventRecord(g_side.evFork, 0);
    cudaStreamWaitEvent(g_side.s2, g_side.evFork, 0);
    gemm64_kernel<0><<<gemm_blocks, dim3(16, 16), 0, g_side.s2>>>(x, W1, gamma, beta);
    cudaEventRecord(g_side.evJoin, g_side.s2);

    // Main branch: CSR build
    zero_kernel<<<node_blocks, TPB>>>();
    degree_kernel<<<edge_blocks, TPB>>>(dst);
    scan1_kernel<<<SCAN_BLOCKS, 256>>>();              // block sums + dinv
    scan23_kernel<<<SCAN_BLOCKS, 256>>>();             // rowptr/cursor
    csr_fill_kernel<<<edge_blocks, TPB>>>(src, dst);

    // Join: aggregate-1 needs both branches
    cudaStreamWaitEvent(0, g_side.evJoin, 0);
    aggregate_kernel<0><<<agg_blocks, TPB>>>(out, b1, batch);
    // layer 2 (BN finalize + BN+ELU fused into gemm X load)
    gemm64_kernel<1><<<gemm_blocks, dim3(16, 16)>>>(x, W2, gamma, beta);
    aggregate_kernel<1><<<agg_blocks, TPB>>>(out, b2, batch);
    // graph readout
    pool_div_kernel<<<(GG * D + TPB - 1) / TPB, TPB>>>(out + (size_t)NN * D);
}

// round 6
// speedup vs baseline: 1.1198x; 1.0245x over previous
#include <cuda_runtime.h>
#include <math.h>

#define NN 50000
#define EE 800000
#define D  64
#define GG 64
#define BN_EPS 1e-5f
#define SCAN_BLOCKS 196   // ceil(50000/256)

// ---------------- device scratch (device-code access only) ----------------
__device__ int   g_degi  [NN];          // zero at load; re-zeroed by scan23 each call
__device__ float g_dinv  [NN];
__device__ int   g_rowptr[NN + 1];      // padded-exclusive scan + sentinel
__device__ int   g_cursor[NN];
__device__ int   g_blocksum[256];
__device__ __align__(16) int2  g_csr[EE + NN];  // (src, coef bits), even-padded per node
__device__ __align__(16) float g_h1 [NN * D];
__device__ __align__(16) float g_agg[NN * D];
__device__ __align__(16) float g_h2 [NN * D];
__device__ float g_bnsum[D];
__device__ float g_bnsq [D];
__device__ __align__(16) float g_pool[GG * D];
__device__ float g_cnt [GG];

// ---------------- packed f32x2 helpers ----------------
__device__ __forceinline__ unsigned long long pack2(float x, float y) {
    unsigned long long r;
    asm("mov.b64 %0, {%1, %2};" : "=l"(r) : "f"(x), "f"(y));
    return r;
}
__device__ __forceinline__ void ffma2(unsigned long long& d,
                                      unsigned long long a, unsigned long long b) {
    asm("fma.rn.f32x2 %0, %1, %2, %0;" : "+l"(d) : "l"(a), "l"(b));
}
__device__ __forceinline__ float2 unpack2(unsigned long long v) {
    float2 f;
    asm("mov.b64 {%0, %1}, %2;" : "=f"(f.x), "=f"(f.y) : "l"(v));
    return f;
}

// ---------------- zero small accumulators (degi handled by scan23) ----------------
__global__ void zero_kernel() {
    int i = blockIdx.x * blockDim.x + threadIdx.x;
    if (i < GG * D) g_pool[i] = 0.f;
    if (i < D)    { g_bnsum[i] = 0.f; g_bnsq[i] = 0.f; }
    if (i < GG)     g_cnt[i] = 0.f;
}

__global__ void degree_kernel(const int* __restrict__ dst) {
    int e = blockIdx.x * blockDim.x + threadIdx.x;
    if (e < EE) atomicAdd(&g_degi[dst[e]], 1);
}

// ---------------- scan phase 1: padded block sums (+ fused dinv) ----------------
__global__ void scan1_kernel() {
    __shared__ int s[256];
    int idx = blockIdx.x * 256 + threadIdx.x;
    int dv = (idx < NN) ? g_degi[idx] : 0;
    if (idx < NN) g_dinv[idx] = rsqrtf((float)dv + 1.0f);
    s[threadIdx.x] = (dv + 1) & ~1;               // pad to even
    __syncthreads();
    for (int o = 128; o > 0; o >>= 1) {
        if (threadIdx.x < o) s[threadIdx.x] += s[threadIdx.x + o];
        __syncthreads();
    }
    if (threadIdx.x == 0) g_blocksum[blockIdx.x] = s[0];
}

// ---------------- scan 2+3 fused: rowptr/cursor, pad slots, degi reset ----------------
__global__ void scan23_kernel() {
    __shared__ int sb[256];
    __shared__ int s[256];
    int t = threadIdx.x;
    sb[t] = (t < SCAN_BLOCKS) ? g_blocksum[t] : 0;
    __syncthreads();
    for (int o = 1; o < 256; o <<= 1) {
        int a = (t >= o) ? sb[t - o] : 0;
        __syncthreads();
        sb[t] += a;
        __syncthreads();
    }
    int blockoff = (blockIdx.x == 0) ? 0 : sb[blockIdx.x - 1];
    int idx = blockIdx.x * 256 + t;
    int v  = (idx < NN) ? g_degi[idx] : 0;
    int vp = (v + 1) & ~1;
    s[t] = vp;
    __syncthreads();
    for (int o = 1; o < 256; o <<= 1) {
        int a = (t >= o) ? s[t - o] : 0;
        __syncthreads();
        s[t] += a;
        __syncthreads();
    }
    if (idx < NN) {
        int rp = blockoff + s[t] - vp;            // exclusive padded offset
        g_rowptr[idx] = rp;
        g_cursor[idx] = rp;
        if (v & 1) g_csr[rp + v] = make_int2(0, 0);  // zero pad entry
        g_degi[idx] = 0;                          // restore invariant for next call
        if (idx == NN - 1) g_rowptr[NN] = blockoff + s[t];  // sentinel
    }
}

// ---------------- CSR fill: packed (src, coef) by dst ----------------
__global__ void csr_fill_kernel(const int* __restrict__ src,
                                const int* __restrict__ dst) {
    int e = blockIdx.x * blockDim.x + threadIdx.x;
    if (e >= EE) return;
    int s = src[e], d = dst[e];
    int pos = atomicAdd(&g_cursor[d], 1);
    float coef = g_dinv[s] * g_dinv[d];
    g_csr[pos] = make_int2(s, __float_as_int(coef));
}

// ---------------- GEMM: Y[NN,64] = X[NN,64] @ W[64,64] (proven shape) ----------------
template<int MODE>
__global__ void gemm64_kernel(const float* __restrict__ Xp,
                              const float* __restrict__ W,
                              const float* __restrict__ gamma,
                              const float* __restrict__ beta) {
    const float* __restrict__ X = (MODE == 0) ? Xp : (const float*)g_agg;
    float* __restrict__       Y = (MODE == 0) ? g_h1 : g_h2;

    __shared__ float sX[64][65];
    __shared__ __align__(16) float sW[64][64];
    __shared__ float s_scale[64], s_shift[64];

    int tid  = threadIdx.y * 16 + threadIdx.x;
    int row0 = blockIdx.x * 64;

    if (MODE == 1) {
        if (tid < 64) {
            float inv_n = 1.0f / (float)NN;
            float mu  = g_bnsum[tid] * inv_n;
            float var = g_bnsq[tid] * inv_n - mu * mu;
            float sc  = gamma[tid] * rsqrtf(var + BN_EPS);
            s_scale[tid] = sc;
            s_shift[tid] = beta[tid] - mu * sc;
        }
        __syncthreads();
    }

    #pragma unroll
    for (int t = tid * 4; t < 4096; t += 1024) {
        *(float4*)(&sW[t >> 6][t & 63]) = *(const float4*)(W + t);
    }
    #pragma unroll
    for (int t = tid * 4; t < 4096; t += 1024) {
        int r = t >> 6, c = t & 63;
        float4 v = make_float4(0.f, 0.f, 0.f, 0.f);
        if (row0 + r < NN) v = *(const float4*)(X + (size_t)(row0 + r) * D + c);
        if (MODE == 1) {
            v.x = v.x * s_scale[c]     + s_shift[c];
            v.y = v.y * s_scale[c + 1] + s_shift[c + 1];
            v.z = v.z * s_scale[c + 2] + s_shift[c + 2];
            v.w = v.w * s_scale[c + 3] + s_shift[c + 3];
            v.x = (v.x > 0.f) ? v.x : (__expf(v.x) - 1.0f);
            v.y = (v.y > 0.f) ? v.y : (__expf(v.y) - 1.0f);
            v.z = (v.z > 0.f) ? v.z : (__expf(v.z) - 1.0f);
            v.w = (v.w > 0.f) ? v.w : (__expf(v.w) - 1.0f);
        }
        sX[r][c] = v.x; sX[r][c + 1] = v.y; sX[r][c + 2] = v.z; sX[r][c + 3] = v.w;
    }
    __syncthreads();

    float acc[4][4] = {};
    int c0 = threadIdx.x * 4, r0 = threadIdx.y * 4;
    #pragma unroll 16
    for (int k = 0; k < 64; k++) {
        float4 w = *(const float4*)(&sW[k][c0]);
        #pragma unroll
        for (int r = 0; r < 4; r++) {
            float xv = sX[r0 + r][k];
            acc[r][0] += xv * w.x; acc[r][1] += xv * w.y;
            acc[r][2] += xv * w.z; acc[r][3] += xv * w.w;
        }
    }
    #pragma unroll
    for (int r = 0; r < 4; r++) {
        int row = row0 + r0 + r;
        if (row < NN)
            *(float4*)(Y + (size_t)row * D + c0) =
                make_float4(acc[r][0], acc[r][1], acc[r][2], acc[r][3]);
    }
}

// ---------------- gather aggregation: warp/node, half-warps, no shfl in loop ----------
// Lanes 0-15 take even edges, 16-31 odd edges (CSR padded even: no tail/predication).
// All 16 lanes of a half load the same g_csr entry (L1 broadcast). Each lane owns a
// float4 feature chunk; accumulate via fma.rn.f32x2; merge halves once at the end.
template<int MODE>
__global__ void aggregate_kernel(float* __restrict__ outp,
                                 const float* __restrict__ bias,
                                 const int* __restrict__ batch) {
    const float* __restrict__ h = (MODE == 0) ? g_h1 : g_h2;
    float* __restrict__ dstbuf  = (MODE == 0) ? g_agg : outp;

    int n    = (blockIdx.x * blockDim.x + threadIdx.x) >> 5;  // grid: n < NN
    int lane = threadIdx.x & 31;
    int half = lane >> 4;
    int fl   = lane & 15;

    int e0 = g_rowptr[n];
    int e1 = g_rowptr[n + 1];     // padded even length

    unsigned long long a0 = 0ull, a1 = 0ull;
    #pragma unroll 4
    for (int e = e0 + half; e < e1; e += 2) {
        int2 ec = g_csr[e];
        float c = __int_as_float(ec.y);
        float4 v = ((const float4*)h)[(size_t)ec.x * 16 + fl];
        unsigned long long cc = pack2(c, c);
        ffma2(a0, cc, pack2(v.x, v.y));
        ffma2(a1, cc, pack2(v.z, v.w));
    }
    float2 f0 = unpack2(a0), f1 = unpack2(a1);
    float4 acc = make_float4(f0.x, f0.y, f1.x, f1.y);
    acc.x += __shfl_xor_sync(0xffffffffu, acc.x, 16);
    acc.y += __shfl_xor_sync(0xffffffffu, acc.y, 16);
    acc.z += __shfl_xor_sync(0xffffffffu, acc.z, 16);
    acc.w += __shfl_xor_sync(0xffffffffu, acc.w, 16);

    // self-loop + bias, store (half 0 owns the row)
    float di = g_dinv[n];
    float cs = di * di;
    if (half == 0) {
        float4 hv = ((const float4*)h)[(size_t)n * 16 + fl];
        float4 bv = ((const float4*)bias)[fl];
        acc.x = fmaf(cs, hv.x, acc.x) + bv.x;
        acc.y = fmaf(cs, hv.y, acc.y) + bv.y;
        acc.z = fmaf(cs, hv.z, acc.z) + bv.z;
        acc.w = fmaf(cs, hv.w, acc.w) + bv.w;
        ((float4*)dstbuf)[(size_t)n * 16 + fl] = acc;
    }

    if (MODE == 0) {
        __shared__ float s_sum[64], s_sq[64];
        if (threadIdx.x < 64) { s_sum[threadIdx.x] = 0.f; s_sq[threadIdx.x] = 0.f; }
        __syncthreads();
        if (half == 0) {
            atomicAdd(&s_sum[fl * 4],     acc.x);
            atomicAdd(&s_sum[fl * 4 + 1], acc.y);
            atomicAdd(&s_sum[fl * 4 + 2], acc.z);
            atomicAdd(&s_sum[fl * 4 + 3], acc.w);
            atomicAdd(&s_sq [fl * 4],     acc.x * acc.x);
            atomicAdd(&s_sq [fl * 4 + 1], acc.y * acc.y);
            atomicAdd(&s_sq [fl * 4 + 2], acc.z * acc.z);
            atomicAdd(&s_sq [fl * 4 + 3], acc.w * acc.w);
        }
        __syncthreads();
        if (threadIdx.x < 64) {
            atomicAdd(&g_bnsum[threadIdx.x], s_sum[threadIdx.x]);
            atomicAdd(&g_bnsq [threadIdx.x], s_sq [threadIdx.x]);
        }
    } else {
        int g = batch[n];
        if (lane == 0) atomicAdd(&g_cnt[g], 1.0f);
        if (half == 0)
            atomicAdd(((float4*)g_pool) + (size_t)g * 16 + fl, acc);
    }
}

__global__ void pool_div_kernel(float* __restrict__ rep) {
    int t = blockIdx.x * blockDim.x + threadIdx.x;
    if (t >= GG * D) return;
    int g = t >> 6;
    rep[t] = g_pool[t] / fmaxf(g_cnt[g], 1.0f);
}

// ---------------- side stream for capture-time fork/join ----------------
struct SideCtx {
    cudaStream_t s2;
    cudaEvent_t evFork, evJoin;
    SideCtx() {
        cudaStreamCreateWithFlags(&s2, cudaStreamNonBlocking);
        cudaEventCreateWithFlags(&evFork, cudaEventDisableTiming);
        cudaEventCreateWithFlags(&evJoin, cudaEventDisableTiming);
    }
};
static SideCtx g_side;

// ---------------- launch ----------------
extern "C" void kernel_launch(void* const* d_in, const int* in_sizes, int n_in,
                              void* d_out, int out_size) {
    const float* x     = (const float*)d_in[0];
    const int*   ei    = (const int*)  d_in[1];
    const int*   batch = (const int*)  d_in[2];
    const float* W1    = (const float*)d_in[3];
    const float* b1    = (const float*)d_in[4];
    const float* gamma = (const float*)d_in[5];
    const float* beta  = (const float*)d_in[6];
    const float* W2    = (const float*)d_in[7];
    const float* b2    = (const float*)d_in[8];
    float* out = (float*)d_out;
    const int* src = ei;
    const int* dst = ei + EE;

    const int TPB = 256;
    int edge_blocks = (EE + TPB - 1) / TPB;            // 3125
    int gemm_blocks = (NN + 63) / 64;                  // 782
    int agg_blocks  = NN / 8;                          // 6250 (warp per node)

    // Fork: GEMM-1 runs concurrently with the CSR build.
    cudaEventRecord(g_side.evFork, 0);
    cudaStreamWaitEvent(g_side.s2, g_side.evFork, 0);
    gemm64_kernel<0><<<gemm_blocks, dim3(16, 16), 0, g_side.s2>>>(x, W1, gamma, beta);
    cudaEventRecord(g_side.evJoin, g_side.s2);

    // Main branch: CSR build (g_degi is zero on entry — invariant)
    zero_kernel<<<16, TPB>>>();
    degree_kernel<<<edge_blocks, TPB>>>(dst);
    scan1_kernel<<<SCAN_BLOCKS, 256>>>();
    scan23_kernel<<<SCAN_BLOCKS, 256>>>();
    csr_fill_kernel<<<edge_blocks, TPB>>>(src, dst);

    // Join, then the serial tail
    cudaStreamWaitEvent(0, g_side.evJoin, 0);
    aggregate_kernel<0><<<agg_blocks, TPB>>>(out, b1, batch);
    gemm64_kernel<1><<<gemm_blocks, dim3(16, 16)>>>(x, W2, gamma, beta);
    aggregate_kernel<1><<<agg_blocks, TPB>>>(out, b2, batch);
    pool_div_kernel<<<16, TPB>>>(out + (size_t)NN * D);
}